// round 1
// baseline (speedup 1.0000x reference)
#include <cuda_runtime.h>

#define KEY_DIM 128
#define NSEG 256

// Scratch: per-segment un-normalized weighted sums + denominators.
// (No cudaMalloc allowed -> __device__ globals.)
__device__ float g_num[NSEG * KEY_DIM];
__device__ float g_den[NSEG];

__global__ void zero_scratch_kernel() {
    int i = blockIdx.x * blockDim.x + threadIdx.x;
    if (i < NSEG * KEY_DIM) g_num[i] = 0.0f;
    if (i < NSEG) g_den[i] = 0.0f;
}

__device__ __forceinline__ void flush_seg(float4 acc, float den, int seg, int lane) {
    float* p = &g_num[seg * KEY_DIM + lane * 4];
    atomicAdd(p + 0, acc.x);
    atomicAdd(p + 1, acc.y);
    atomicAdd(p + 2, acc.z);
    atomicAdd(p + 3, acc.w);
    if (lane == 0) atomicAdd(&g_den[seg], den);
}

// One warp processes a contiguous run of nodes. batch_index is sorted, so the
// segment id changes rarely; accumulate e*feat in registers, flush on change.
// No max-subtraction: scores ~ N(0,1), exp() cannot overflow fp32, and
// softmax is shift-invariant.
__global__ void __launch_bounds__(256, 4) seg_attn_main(
    const float* __restrict__ feats,
    const float* __restrict__ Qm,
    const int*   __restrict__ bidx,
    int V, int nodes_per_warp)
{
    int gw   = (blockIdx.x * blockDim.x + threadIdx.x) >> 5;
    int lane = threadIdx.x & 31;
    int start = gw * nodes_per_warp;
    if (start >= V) return;
    int end = min(V, start + nodes_per_warp);

    const float4* fq = reinterpret_cast<const float4*>(Qm);    // [256][32]
    const float4* ff = reinterpret_cast<const float4*>(feats); // [V][32]

    int cur = bidx[start];
    float4 q   = fq[cur * 32 + lane];
    float4 acc = make_float4(0.f, 0.f, 0.f, 0.f);
    float  den = 0.f;
    const float scale = 0.08838834764831845f;  // 1/sqrt(128)

    // Software pipeline: prefetch next node's row + segment id (MLP=2).
    int    i  = start;
    int    nb = cur;
    float4 f  = ff[i * 32 + lane];

    while (i < end) {
        float4 fcur = f;
        int    b    = nb;
        int    j    = i + 1;
        if (j < end) {
            nb = bidx[j];
            f  = ff[j * 32 + lane];
        }
        if (b != cur) {
            flush_seg(acc, den, cur, lane);
            acc = make_float4(0.f, 0.f, 0.f, 0.f);
            den = 0.f;
            cur = b;
            q   = fq[cur * 32 + lane];
        }
        // Per-lane partial dot over 4 dims, butterfly reduce to full dot.
        float p = fcur.x * q.x + fcur.y * q.y + fcur.z * q.z + fcur.w * q.w;
        p += __shfl_xor_sync(0xffffffffu, p, 16);
        p += __shfl_xor_sync(0xffffffffu, p, 8);
        p += __shfl_xor_sync(0xffffffffu, p, 4);
        p += __shfl_xor_sync(0xffffffffu, p, 2);
        p += __shfl_xor_sync(0xffffffffu, p, 1);

        float e = __expf(p * scale);
        acc.x += e * fcur.x;
        acc.y += e * fcur.y;
        acc.z += e * fcur.z;
        acc.w += e * fcur.w;
        den   += e;   // identical in all lanes; only lane 0's copy is flushed

        i = j;
    }
    flush_seg(acc, den, cur, lane);
}

__global__ void finalize_kernel(float* __restrict__ out) {
    int b = blockIdx.x;   // 0..255
    int d = threadIdx.x;  // 0..127
    float den = g_den[b];
    float v = (den > 0.f) ? (g_num[b * KEY_DIM + d] / den) : 0.f;
    out[b * KEY_DIM + d] = v;
}

extern "C" void kernel_launch(void* const* d_in, const int* in_sizes, int n_in,
                              void* d_out, int out_size) {
    const float* feats = (const float*)d_in[0];   // [V,128] fp32
    const float* Qm    = (const float*)d_in[1];   // [256,128] fp32
    const int*   bidx  = (const int*)d_in[2];     // [V] int32, sorted
    int V = in_sizes[2];
    float* out = (float*)d_out;                   // [V,128] fp32

    // 1) Zero the full output (rows >= B must be 0; buffer is poisoned).
    cudaMemsetAsync(d_out, 0, (size_t)out_size * sizeof(float), 0);

    // 2) Zero per-segment scratch (graph replays -> must be reset every call).
    zero_scratch_kernel<<<(NSEG * KEY_DIM + 255) / 256, 256>>>();

    // 3) Fused scores + exp + weighted accumulation (single pass over feats).
    const int blocks = 592;           // 4 blocks/SM x 148 SMs
    const int warps  = blocks * 8;    // 256 threads/block
    int npw = (V + warps - 1) / warps;
    seg_attn_main<<<blocks, 256>>>(feats, Qm, bidx, V, npw);

    // 4) Normalize and write the 256 live rows.
    finalize_kernel<<<NSEG, KEY_DIM>>>(out);
}

// round 3
// speedup vs baseline: 1.2184x; 1.2184x over previous
#include <cuda_runtime.h>

#define KEY_DIM 128
#define NSEG 256

// Scratch: per-segment un-normalized weighted sums + denominators.
__device__ float g_num[NSEG * KEY_DIM];
__device__ float g_den[NSEG];

__global__ void zero_scratch_kernel() {
    int i = blockIdx.x * blockDim.x + threadIdx.x;
    if (i < NSEG * KEY_DIM) g_num[i] = 0.0f;
    if (i < NSEG) g_den[i] = 0.0f;
}

__device__ __forceinline__ void flush_seg(float4 acc, float den, int seg, int lane) {
    float* p = &g_num[seg * KEY_DIM + lane * 4];
    atomicAdd(p + 0, acc.x);
    atomicAdd(p + 1, acc.y);
    atomicAdd(p + 2, acc.z);
    atomicAdd(p + 3, acc.w);
    if (lane == 0) atomicAdd(&g_den[seg], den);
}

// One warp owns a contiguous, 4-aligned run of sorted nodes. Per batch of 4:
// issue 4 independent 512B row loads (MLP=4) + 1 int4 index load, then do
// dot/exp/accumulate, and store 512B of zeros to the matching output rows
// (fuses the 512MB output clear into this kernel -> mixed R/W DRAM traffic).
__global__ void __launch_bounds__(256, 4) seg_attn_main(
    const float* __restrict__ feats,
    const float* __restrict__ Qm,
    const int*   __restrict__ bidx,
    float*       __restrict__ out,
    int V, int nodes_per_warp)
{
    int gw   = (blockIdx.x * blockDim.x + threadIdx.x) >> 5;
    int lane = threadIdx.x & 31;
    int start = gw * nodes_per_warp;          // nodes_per_warp is a multiple of 4
    if (start >= V) return;
    int end = min(V, start + nodes_per_warp);

    const float4* fq = reinterpret_cast<const float4*>(Qm);    // [256][32]
    const float4* ff = reinterpret_cast<const float4*>(feats); // [V][32]
    float4*       fo = reinterpret_cast<float4*>(out);         // [V][32]
    const float4  z4 = make_float4(0.f, 0.f, 0.f, 0.f);

    int cur = bidx[start];
    float4 q   = fq[cur * 32 + lane];
    float4 acc = make_float4(0.f, 0.f, 0.f, 0.f);
    float  den = 0.f;
    const float scale = 0.08838834764831845f;  // 1/sqrt(128)

    int i = start;
    // Full batches of 4 (start is 4-aligned).
    for (; i + 4 <= end; i += 4) {
        int4   b4 = *reinterpret_cast<const int4*>(&bidx[i]);
        float4 f0 = ff[(i + 0) * 32 + lane];
        float4 f1 = ff[(i + 1) * 32 + lane];
        float4 f2 = ff[(i + 2) * 32 + lane];
        float4 f3 = ff[(i + 3) * 32 + lane];

        int    bs[4] = {b4.x, b4.y, b4.z, b4.w};
        float4 fs[4] = {f0, f1, f2, f3};

        #pragma unroll
        for (int k = 0; k < 4; k++) {
            int    b = bs[k];
            float4 f = fs[k];
            if (b != cur) {
                flush_seg(acc, den, cur, lane);
                acc = make_float4(0.f, 0.f, 0.f, 0.f);
                den = 0.f;
                cur = b;
                q   = fq[cur * 32 + lane];
            }
            float p = f.x * q.x + f.y * q.y + f.z * q.z + f.w * q.w;
            p += __shfl_xor_sync(0xffffffffu, p, 16);
            p += __shfl_xor_sync(0xffffffffu, p, 8);
            p += __shfl_xor_sync(0xffffffffu, p, 4);
            p += __shfl_xor_sync(0xffffffffu, p, 2);
            p += __shfl_xor_sync(0xffffffffu, p, 1);

            float e = __expf(p * scale);
            acc.x += e * f.x;
            acc.y += e * f.y;
            acc.z += e * f.z;
            acc.w += e * f.w;
            den   += e;

            fo[(i + k) * 32 + lane] = z4;   // fused output clear
        }
    }
    // Tail (< 4 nodes, or V not 4-aligned).
    for (; i < end; i++) {
        int    b = bidx[i];
        float4 f = ff[i * 32 + lane];
        if (b != cur) {
            flush_seg(acc, den, cur, lane);
            acc = make_float4(0.f, 0.f, 0.f, 0.f);
            den = 0.f;
            cur = b;
            q   = fq[cur * 32 + lane];
        }
        float p = f.x * q.x + f.y * q.y + f.z * q.z + f.w * q.w;
        p += __shfl_xor_sync(0xffffffffu, p, 16);
        p += __shfl_xor_sync(0xffffffffu, p, 8);
        p += __shfl_xor_sync(0xffffffffu, p, 4);
        p += __shfl_xor_sync(0xffffffffu, p, 2);
        p += __shfl_xor_sync(0xffffffffu, p, 1);
        float e = __expf(p * scale);
        acc.x += e * f.x;
        acc.y += e * f.y;
        acc.z += e * f.z;
        acc.w += e * f.w;
        den   += e;
        fo[i * 32 + lane] = z4;
    }
    flush_seg(acc, den, cur, lane);
}

__global__ void finalize_kernel(float* __restrict__ out) {
    int b = blockIdx.x;   // 0..255
    int d = threadIdx.x;  // 0..127
    float den = g_den[b];
    float v = (den > 0.f) ? (g_num[b * KEY_DIM + d] / den) : 0.f;
    out[b * KEY_DIM + d] = v;
}

extern "C" void kernel_launch(void* const* d_in, const int* in_sizes, int n_in,
                              void* d_out, int out_size) {
    const float* feats = (const float*)d_in[0];   // [V,128] fp32
    const float* Qm    = (const float*)d_in[1];   // [256,128] fp32
    const int*   bidx  = (const int*)d_in[2];     // [V] int32, sorted
    int V = in_sizes[2];
    float* out = (float*)d_out;                   // [V,128] fp32

    // 1) Zero per-segment scratch (graph replays -> must reset every call).
    zero_scratch_kernel<<<(NSEG * KEY_DIM + 255) / 256, 256>>>();

    // 2) Fused: scores + exp + weighted accumulation + output zeroing
    //    (single pass: 512MB read + 512MB write, mixed DRAM traffic).
    const int blocks = 592;           // 4 blocks/SM x 148 SMs
    const int warps  = blocks * 8;    // 256 threads/block
    int npw = (V + warps - 1) / warps;
    npw = (npw + 3) & ~3;             // 4-aligned so int4 index loads are aligned
    seg_attn_main<<<blocks, 256>>>(feats, Qm, bidx, out, V, npw);

    // 3) Normalize and write the 256 live rows.
    finalize_kernel<<<NSEG, KEY_DIM>>>(out);
}